// round 7
// baseline (speedup 1.0000x reference)
#include <cuda_runtime.h>
#include <cuda_bf16.h>

#define BB 16
#define NN 32768
#define CC 64
#define RR 32
#define R3 (RR*RR*RR)
#define EPSF 1e-6f

#define PREP_BLKS 256                 // persistent prep kernel blocks
#define BLKS_PER_BATCH (PREP_BLKS/BB) // 16
#define PTS_PER_BLK (NN/BLKS_PER_BATCH) // 2048
#define PTS_PER_THR (PTS_PER_BLK/256)   // 8

// Scratch (device globals — zero-initialized at load; no allocation allowed)
__device__ __align__(16) int g_cnt[BB * R3];    // points per voxel (re-zeroed by k_gather)
__device__ __align__(16) int g_cursor[BB * R3]; // reorder cursor (ends at start+cnt)
__device__ int   g_order[BB * NN];              // point ids grouped by voxel
__device__ float g_part[PREP_BLKS][3];          // partial coord sums
__device__ int   g_maxsq[BB];                   // max squared norm, float bits (>=0)
__device__ int   g_bsum[PREP_BLKS];             // per-block count sums

// Software grid barrier (replay-safe: generation counter is monotonic)
__device__ unsigned g_gen = 0;
__device__ unsigned g_arrive = 0;

__device__ __forceinline__ void grid_bar() {
    __syncthreads();
    if (threadIdx.x == 0) {
        __threadfence();
        unsigned gen = *(volatile unsigned*)&g_gen;
        if (atomicAdd(&g_arrive, 1u) == PREP_BLKS - 1) {
            g_arrive = 0;
            __threadfence();
            atomicAdd(&g_gen, 1u);      // release
        } else {
            while (*(volatile unsigned*)&g_gen == gen) __nanosleep(64);
        }
        __threadfence();
    }
    __syncthreads();
}

// ---------------------------------------------------------------------------
// ONE persistent kernel: mean -> maxnorm -> points -> blocksum -> scan ->
// reorder, separated by grid barriers. Coords + voxel indices live in regs.
// ---------------------------------------------------------------------------
__global__ void __launch_bounds__(256, 2)
k_prep(const float* __restrict__ coords, float* __restrict__ out_nc, int write_nc) {
    const int blk = blockIdx.x;                    // 0..255
    const int b   = blk / BLKS_PER_BATCH;
    const int tid = threadIdx.x;
    const int lane = tid & 31, w = tid >> 5;
    const int t0  = blk * PTS_PER_BLK + tid * PTS_PER_THR;  // global point base

    __shared__ float shf[3][8];
    __shared__ float smean[3];
    __shared__ float sden_s;
    __shared__ int   wsum[8];
    __shared__ int   sboff_s;

    // ---- load this thread's 8 points (24 floats = 6 float4) ----
    float c[24];
    {
        const float4* cp = reinterpret_cast<const float4*>(coords + (size_t)t0 * 3);
        #pragma unroll
        for (int i = 0; i < 6; i++) {
            float4 v = cp[i];
            c[i*4+0] = v.x; c[i*4+1] = v.y; c[i*4+2] = v.z; c[i*4+3] = v.w;
        }
    }

    // ================= Phase A: partial mean (+ reset maxsq) =================
    if (tid == 0 && (blk % BLKS_PER_BATCH) == 0) g_maxsq[b] = 0;
    {
        float sx = 0.f, sy = 0.f, sz = 0.f;
        #pragma unroll
        for (int i = 0; i < PTS_PER_THR; i++) {
            sx += c[i*3+0]; sy += c[i*3+1]; sz += c[i*3+2];
        }
        #pragma unroll
        for (int off = 16; off; off >>= 1) {
            sx += __shfl_down_sync(0xffffffffu, sx, off);
            sy += __shfl_down_sync(0xffffffffu, sy, off);
            sz += __shfl_down_sync(0xffffffffu, sz, off);
        }
        if (lane == 0) { shf[0][w] = sx; shf[1][w] = sy; shf[2][w] = sz; }
        __syncthreads();
        if (tid == 0) {
            float ax = 0.f, ay = 0.f, az = 0.f;
            #pragma unroll
            for (int k = 0; k < 8; k++) { ax += shf[0][k]; ay += shf[1][k]; az += shf[2][k]; }
            g_part[blk][0] = ax; g_part[blk][1] = ay; g_part[blk][2] = az;
        }
    }
    grid_bar();

    // ================= Phase B: max centered squared norm =================
    if (tid < 3) {
        float s = 0.f;
        #pragma unroll
        for (int k = 0; k < BLKS_PER_BATCH; k++)
            s += g_part[b * BLKS_PER_BATCH + k][tid];
        smean[tid] = s / (float)NN;
    }
    __syncthreads();
    const float mx = smean[0], my = smean[1], mz = smean[2];
    {
        float m = 0.f;
        #pragma unroll
        for (int i = 0; i < PTS_PER_THR; i++) {
            float dx = c[i*3+0] - mx;
            float dy = c[i*3+1] - my;
            float dz = c[i*3+2] - mz;
            m = fmaxf(m, dx*dx + dy*dy + dz*dz);
        }
        #pragma unroll
        for (int off = 16; off; off >>= 1)
            m = fmaxf(m, __shfl_down_sync(0xffffffffu, m, off));
        if (lane == 0) shf[0][w] = m;
        __syncthreads();
        if (tid == 0) {
            #pragma unroll
            for (int k = 0; k < 8; k++) m = fmaxf(m, shf[0][k]);
            atomicMax(&g_maxsq[b], __float_as_int(m));  // m>=0: int order == float order
        }
    }
    grid_bar();

    // ================= Phase C: normalized coords + idx + counts =================
    if (tid == 0)
        sden_s = __fmaf_rn(2.f, __fsqrt_rn(__int_as_float(g_maxsq[b])), EPSF);
    __syncthreads();
    const float d = sden_s;

    float nc[24];
    int vidx[PTS_PER_THR];
    #pragma unroll
    for (int i = 0; i < PTS_PER_THR; i++) {
        const float nx = __fadd_rn(__fdiv_rn(__fsub_rn(c[i*3+0], mx), d), 0.5f);
        const float ny = __fadd_rn(__fdiv_rn(__fsub_rn(c[i*3+1], my), d), 0.5f);
        const float nz = __fadd_rn(__fdiv_rn(__fsub_rn(c[i*3+2], mz), d), 0.5f);
        nc[i*3+0] = nx; nc[i*3+1] = ny; nc[i*3+2] = nz;

        int vx = __float2int_rn(__fmul_rn(nx, (float)(RR - 1)));
        int vy = __float2int_rn(__fmul_rn(ny, (float)(RR - 1)));
        int vz = __float2int_rn(__fmul_rn(nz, (float)(RR - 1)));
        vx = min(max(vx, 0), RR - 1);
        vy = min(max(vy, 0), RR - 1);
        vz = min(max(vz, 0), RR - 1);
        const int idx = vx * (RR * RR) + vy * RR + vz;
        vidx[i] = idx;
        atomicAdd(&g_cnt[b * R3 + idx], 1);
    }
    if (write_nc) {
        float4* np = reinterpret_cast<float4*>(out_nc + (size_t)t0 * 3);
        #pragma unroll
        for (int i = 0; i < 6; i++)
            np[i] = make_float4(nc[i*4+0], nc[i*4+1], nc[i*4+2], nc[i*4+3]);
    }
    grid_bar();

    // ================= Phase D: block count sums (counts -> regs) =================
    int cnts[8];
    int tsum;
    {
        const int4* c4 = reinterpret_cast<const int4*>(g_cnt);
        const int i4 = blk * (PTS_PER_BLK / 4) + tid * 2;  // 2048 counts per block
        int4 v0 = c4[i4], v1 = c4[i4 + 1];
        cnts[0]=v0.x; cnts[1]=v0.y; cnts[2]=v0.z; cnts[3]=v0.w;
        cnts[4]=v1.x; cnts[5]=v1.y; cnts[6]=v1.z; cnts[7]=v1.w;
        tsum = cnts[0]+cnts[1]+cnts[2]+cnts[3]+cnts[4]+cnts[5]+cnts[6]+cnts[7];
        int s = tsum;
        #pragma unroll
        for (int off = 16; off; off >>= 1)
            s += __shfl_down_sync(0xffffffffu, s, off);
        if (lane == 0) wsum[w] = s;
        __syncthreads();
        if (tid == 0) {
            int t = 0;
            #pragma unroll
            for (int k = 0; k < 8; k++) t += wsum[k];
            g_bsum[blk] = t;
        }
        __syncthreads();   // wsum reused below
    }
    grid_bar();

    // ================= Phase E: cursors (exclusive scan) =================
    {
        // block offset: warp-scan the 16 block sums of this batch
        if (tid < 32) {
            int v = (tid < BLKS_PER_BATCH) ? g_bsum[b * BLKS_PER_BATCH + tid] : 0;
            int inc = v;
            #pragma unroll
            for (int off = 1; off < 32; off <<= 1) {
                int u = __shfl_up_sync(0xffffffffu, inc, off);
                if (tid >= off) inc += u;
            }
            if (tid == (blk % BLKS_PER_BATCH)) sboff_s = b * NN + inc - v;
        }
        // block-wide exclusive scan of per-thread tsum
        int inc = tsum;
        #pragma unroll
        for (int off = 1; off < 32; off <<= 1) {
            int u = __shfl_up_sync(0xffffffffu, inc, off);
            if (lane >= off) inc += u;
        }
        if (lane == 31) wsum[w] = inc;
        __syncthreads();   // also publishes sboff_s
        int woff = 0;
        #pragma unroll
        for (int k = 0; k < 8; k++) woff += (k < w) ? wsum[k] : 0;

        int base = sboff_s + woff + inc - tsum;
        int4 u0, u1;
        u0.x = base;
        u0.y = u0.x + cnts[0];
        u0.z = u0.y + cnts[1];
        u0.w = u0.z + cnts[2];
        u1.x = u0.w + cnts[3];
        u1.y = u1.x + cnts[4];
        u1.z = u1.y + cnts[5];
        u1.w = u1.z + cnts[6];
        int4* q4 = reinterpret_cast<int4*>(g_cursor);
        const int i4 = blk * (PTS_PER_BLK / 4) + tid * 2;
        q4[i4] = u0;
        q4[i4 + 1] = u1;
    }
    grid_bar();

    // ================= Phase F: reorder (idx still in regs) =================
    #pragma unroll
    for (int i = 0; i < PTS_PER_THR; i++) {
        const int slot = atomicAdd(&g_cursor[b * R3 + vidx[i]], 1);
        g_order[slot] = t0 + i;
    }
}

// ---------------------------------------------------------------------------
// Fused gather + mean + transpose (unchanged from R6 — proven).
// ---------------------------------------------------------------------------
__global__ void k_gather(const float* __restrict__ features,
                         float* __restrict__ out) {
    const int b  = blockIdx.y;
    const int v0 = blockIdx.x * 32;
    const int tx = threadIdx.x;           // 0..7
    const int ty = threadIdx.y;           // 0..31
    const int seg = b * R3 + v0 + ty;

    const int cnt   = g_cnt[seg];
    const int start = g_cursor[seg] - cnt;
    const float4* f4 = reinterpret_cast<const float4*>(features);

    float4 a0 = make_float4(0.f, 0.f, 0.f, 0.f);
    float4 a1 = make_float4(0.f, 0.f, 0.f, 0.f);

    int j = 0;
    for (; j + 2 <= cnt; j += 2) {
        const int p0 = g_order[start + j];
        const int p1 = g_order[start + j + 1];
        const float4 x0 = __ldcs(&f4[(size_t)p0 * (CC / 4) + tx]);
        const float4 y0 = __ldcs(&f4[(size_t)p0 * (CC / 4) + tx + 8]);
        const float4 x1 = __ldcs(&f4[(size_t)p1 * (CC / 4) + tx]);
        const float4 y1 = __ldcs(&f4[(size_t)p1 * (CC / 4) + tx + 8]);
        a0.x += x0.x + x1.x; a0.y += x0.y + x1.y;
        a0.z += x0.z + x1.z; a0.w += x0.w + x1.w;
        a1.x += y0.x + y1.x; a1.y += y0.y + y1.y;
        a1.z += y0.z + y1.z; a1.w += y0.w + y1.w;
    }
    if (j < cnt) {
        const int p0 = g_order[start + j];
        const float4 x0 = __ldcs(&f4[(size_t)p0 * (CC / 4) + tx]);
        const float4 y0 = __ldcs(&f4[(size_t)p0 * (CC / 4) + tx + 8]);
        a0.x += x0.x; a0.y += x0.y; a0.z += x0.z; a0.w += x0.w;
        a1.x += y0.x; a1.y += y0.y; a1.z += y0.z; a1.w += y0.w;
    }

    const float inv = 1.0f / (float)max(cnt, 1);
    a0.x *= inv; a0.y *= inv; a0.z *= inv; a0.w *= inv;
    a1.x *= inv; a1.y *= inv; a1.z *= inv; a1.w *= inv;

    __shared__ float sh[CC][33];
    sh[tx * 4 + 0][ty] = a0.x;
    sh[tx * 4 + 1][ty] = a0.y;
    sh[tx * 4 + 2][ty] = a0.z;
    sh[tx * 4 + 3][ty] = a0.w;
    sh[(tx + 8) * 4 + 0][ty] = a1.x;
    sh[(tx + 8) * 4 + 1][ty] = a1.y;
    sh[(tx + 8) * 4 + 2][ty] = a1.z;
    sh[(tx + 8) * 4 + 3][ty] = a1.w;
    __syncthreads();

    const int tid = ty * 8 + tx;
    const int lane = tid & 31;
    #pragma unroll
    for (int r = 0; r < 8; r++) {
        const int c = (tid >> 5) + r * 8;
        __stcs(&out[((size_t)b * CC + c) * R3 + v0 + lane], sh[c][lane]);
    }

    // reset counts for the next replay
    if (tid < 32) g_cnt[b * R3 + v0 + tid] = 0;
}

// ---------------------------------------------------------------------------
extern "C" void kernel_launch(void* const* d_in, const int* in_sizes, int n_in,
                              void* d_out, int out_size) {
    const float* features = (const float*)d_in[0];
    const float* coords   = (const float*)d_in[1];
    float* out = (float*)d_out;

    const size_t avg_elems = (size_t)BB * CC * R3;
    const size_t nc_elems  = (size_t)BB * NN * 3;
    const int write_nc = ((size_t)out_size >= avg_elems + nc_elems) ? 1 : 0;
    float* out_nc = out + avg_elems;

    k_prep<<<PREP_BLKS, 256>>>(coords, out_nc, write_nc);
    {
        dim3 grid(R3 / 32, BB);
        dim3 block(8, 32);
        k_gather<<<grid, block>>>(features, out);
    }
}